// round 14
// baseline (speedup 1.0000x reference)
#include <cuda_runtime.h>
#include <cuda_fp16.h>
#include <mma.h>

using namespace nvcuda;

#define Bsz  4096
#define Nseq 512
#define Csz  512
#define PHId 128
#define H1d  512
#define H2d  256

// Scratch (__device__ globals; no allocations allowed)
__device__ __half g_hist [Bsz * Csz];    // 4 MB   per-row label histogram (fp16, exact)
__device__ __half g_h1   [Bsz * H1d];    // 4 MB
__device__ float  g_part [4 * Bsz];      // partial dots (deterministic reduce)
__device__ __half g_Wc   [Csz * H1d];    // 512 KB  Wc = Wphi @ W1 (fp16)
__device__ __half g_W2   [H1d * H2d];
__device__ float  g_b1eff[H1d];          // b1 + 512 * (b_phi @ W1), exact fp32

// ---------------------------------------------------------------------------
// cp.async helpers (LDGSTS, 16B)
// ---------------------------------------------------------------------------
__device__ __forceinline__ void cp_async16(void* smem, const void* gmem) {
    unsigned s = (unsigned)__cvta_generic_to_shared(smem);
    asm volatile("cp.async.cg.shared.global [%0], [%1], 16;\n" :: "r"(s), "l"(gmem));
}
__device__ __forceinline__ void cp_commit() {
    asm volatile("cp.async.commit_group;\n");
}
template <int NN>
__device__ __forceinline__ void cp_wait() {
    asm volatile("cp.async.wait_group %0;\n" :: "n"(NN));
}

// ---------------------------------------------------------------------------
// Histogram kernel: 4 rows/block, 128 threads, one warp per row, smem atomics.
// Grid 512 blocks covers 2048 rows starting at rowOff.
// ---------------------------------------------------------------------------
__global__ void __launch_bounds__(128) hist_kernel(const int* __restrict__ x,
                                                   int rowOff)
{
    __shared__ int hs[4 * Csz];   // 8 KB
    const int tid = threadIdx.x;
#pragma unroll
    for (int i = 0; i < 4; i++)
        reinterpret_cast<int4*>(hs)[tid + i * 128] = make_int4(0, 0, 0, 0);
    __syncthreads();

    const int warp = tid >> 5, lane = tid & 31;
    const int row = rowOff + blockIdx.x * 4 + warp;
    const int4* xr = reinterpret_cast<const int4*>(x + (size_t)row * Nseq);
    int* hw = hs + warp * Csz;
#pragma unroll
    for (int i = 0; i < 4; i++) {            // 128 int4 per row
        const int4 v = xr[lane + i * 32];
        atomicAdd(&hw[v.x], 1);
        atomicAdd(&hw[v.y], 1);
        atomicAdd(&hw[v.z], 1);
        atomicAdd(&hw[v.w], 1);
    }
    __syncthreads();

    __half* dst = g_hist + ((size_t)rowOff + blockIdx.x * 4) * Csz;
#pragma unroll
    for (int i = 0; i < 4; i++) {
        const int e4 = tid + i * 128;
        const int4 c = reinterpret_cast<const int4*>(hs)[e4];
        __half h4[4] = {__float2half((float)c.x), __float2half((float)c.y),
                        __float2half((float)c.z), __float2half((float)c.w)};
        *reinterpret_cast<uint2*>(&dst[e4 * 4]) = *reinterpret_cast<uint2*>(h4);
    }
}

// ---------------------------------------------------------------------------
// Weight-prep kernel (97 blocks):
//   [0,64)  : Wc = Wphi @ W1 via wmma HMMA (fp16 in, fp32 acc), 64x64/block
//   [64,96) : W2 fp32 -> fp16 convert
//   96      : b1_eff = b1 + 512*(b_phi @ W1) in fp32
// ---------------------------------------------------------------------------
__global__ void __launch_bounds__(256) prepw_kernel(const float* __restrict__ Wphi,
                                                    const float* __restrict__ W1,
                                                    const float* __restrict__ W2,
                                                    const float* __restrict__ bphi,
                                                    const float* __restrict__ b1)
{
    __shared__ __align__(16) char praw[35840];
    const int tid = threadIdx.x;

    if (blockIdx.x < 64) {
        // Wc tile 64x64, K=128. smem: A[64][136]h, B[128][72]h
        const int cb = blockIdx.x;                     // 0..63 -> 8x8 tiles
        const int tr = (cb >> 3) * 64, tcc = (cb & 7) * 64;
        __half* sA = reinterpret_cast<__half*>(praw);           // ld 136
        __half* sB = reinterpret_cast<__half*>(praw + 17408);   // ld 72
        float*  sC = reinterpret_cast<float*>(praw);            // ld 68 (aliases sA)

#pragma unroll
        for (int i = 0; i < 8; i++) {
            const int idx = i * 256 + tid;
            const int r = idx >> 5, c4 = (idx & 31) << 2;
            const float4 v = *reinterpret_cast<const float4*>(
                &Wphi[(size_t)(tr + r) * PHId + c4]);
            __half h4[4] = {__float2half(v.x), __float2half(v.y),
                            __float2half(v.z), __float2half(v.w)};
            *reinterpret_cast<uint2*>(&sA[r * 136 + c4]) = *reinterpret_cast<uint2*>(h4);
        }
#pragma unroll
        for (int i = 0; i < 8; i++) {
            const int idx = i * 256 + tid;
            const int r = idx >> 4, c4 = (idx & 15) << 2;
            const float4 v = *reinterpret_cast<const float4*>(
                &W1[(size_t)r * H1d + tcc + c4]);
            __half h4[4] = {__float2half(v.x), __float2half(v.y),
                            __float2half(v.z), __float2half(v.w)};
            *reinterpret_cast<uint2*>(&sB[r * 72 + c4]) = *reinterpret_cast<uint2*>(h4);
        }
        __syncthreads();

        // 8 warps: 2 row-groups x 4 col-groups; warp tile 32x16
        const int wrp = tid >> 5, wr2 = wrp & 1, wc2 = wrp >> 1;
        wmma::fragment<wmma::accumulator, 16, 16, 16, float> ac[2];
        wmma::fill_fragment(ac[0], 0.f);
        wmma::fill_fragment(ac[1], 0.f);
#pragma unroll
        for (int k = 0; k < 8; k++) {
            wmma::fragment<wmma::matrix_a, 16, 16, 16, __half, wmma::row_major> af[2];
            wmma::fragment<wmma::matrix_b, 16, 16, 16, __half, wmma::row_major> bf;
            wmma::load_matrix_sync(af[0], &sA[(wr2 * 32) * 136 + k * 16], 136);
            wmma::load_matrix_sync(af[1], &sA[(wr2 * 32 + 16) * 136 + k * 16], 136);
            wmma::load_matrix_sync(bf, &sB[(k * 16) * 72 + wc2 * 16], 72);
            wmma::mma_sync(ac[0], af[0], bf, ac[0]);
            wmma::mma_sync(ac[1], af[1], bf, ac[1]);
        }
        __syncthreads();       // done reading sA before aliasing as sC
        wmma::store_matrix_sync(&sC[(wr2 * 32) * 68 + wc2 * 16], ac[0], 68,
                                wmma::mem_row_major);
        wmma::store_matrix_sync(&sC[(wr2 * 32 + 16) * 68 + wc2 * 16], ac[1], 68,
                                wmma::mem_row_major);
        __syncthreads();

#pragma unroll
        for (int e = tid; e < 64 * 8; e += 256) {
            const int r = e >> 3, c = (e & 7) << 3;
            __half h8[8];
#pragma unroll
            for (int q = 0; q < 8; q++) h8[q] = __float2half(sC[r * 68 + c + q]);
            *reinterpret_cast<int4*>(&g_Wc[(size_t)(tr + r) * H1d + tcc + c]) =
                *reinterpret_cast<int4*>(h8);
        }
    } else if (blockIdx.x < 96) {
        // W2 convert: 8192 threads, 32768 float4 -> 4 per thread
        const int t = (blockIdx.x - 64) * 256 + tid;
#pragma unroll
        for (int i = 0; i < 4; i++) {
            const int e4 = t + i * 8192;
            const float4 v = reinterpret_cast<const float4*>(W2)[e4];
            __half h4[4] = {__float2half(v.x), __float2half(v.y),
                            __float2half(v.z), __float2half(v.w)};
            *reinterpret_cast<uint2*>(&g_W2[e4 * 4]) = *reinterpret_cast<uint2*>(h4);
        }
    } else {
#pragma unroll
        for (int o = tid; o < H1d; o += 256) {
            float s = 0.f;
            for (int k = 0; k < PHId; k++) s = fmaf(bphi[k], W1[k * H1d + o], s);
            g_b1eff[o] = b1[o] + (float)Nseq * s;
        }
    }
}

// ---------------------------------------------------------------------------
// Pipelined fp16 tensor-core GEMM, fp32 accumulate, fused bias+ReLU epilogue.
// BM=64, BN=64, BK=64; 128 threads = 4 warps (2x2), warp tile 32x32.
// 2-stage cp.async pipeline, ONE __syncthreads per k-iteration.
// rowOff selects the batch-row half this launch covers.
// FUSED: epilogue computes relu(acc+bias) dot W3-slice -> g_part.
// ---------------------------------------------------------------------------
template <bool FUSED>
__global__ void __launch_bounds__(128) gemm_tc(const __half* __restrict__ A,
                                               const __half* __restrict__ B,
                                               const float* __restrict__ bias,
                                               const float* __restrict__ W3,
                                               __half* __restrict__ C,
                                               int rowOff, int M, int N, int K)
{
    constexpr int BM = 64, BN = 64, BK = 64, T = 128;
    __shared__ __align__(16) union USM {
        struct { __half A[2][BM][BK + 8]; __half B[2][BK][BN + 8]; } in;   // 36 KB
        float Cs[BM][BN + 4];
    } sm;
    __shared__ float w3s[BN];
    __shared__ float bs[BN];
    __shared__ float sp[BM][2];

    const int tid  = threadIdx.x;
    const int warp = tid >> 5;
    const int wr   = warp & 1;      // row group: 32 rows
    const int wc   = warp >> 1;     // col group: 32 cols
    const int rowBase = rowOff + blockIdx.y * BM;
    const int colBase = blockIdx.x * BN;

    if (FUSED && tid < BN) {
        w3s[tid] = W3[colBase + tid];
        bs[tid]  = bias[colBase + tid];
    }

    // loader map: 64 rows x 8 chunks(16B) = 512 chunks, 4 per thread
    const int lr = tid >> 3, lc = (tid & 7) << 3;

    auto load_tile = [&](int s, int kt) {
        const __half* Ak = A + (size_t)rowBase * K + kt * BK;
#pragma unroll
        for (int r = 0; r < 4; r++)
            cp_async16(&sm.in.A[s][lr + 16 * r][lc], Ak + (size_t)(lr + 16 * r) * K + lc);
        const __half* Bk = B + (size_t)(kt * BK) * N + colBase;
#pragma unroll
        for (int r = 0; r < 4; r++)
            cp_async16(&sm.in.B[s][lr + 16 * r][lc], Bk + (size_t)(lr + 16 * r) * N + lc);
    };

    wmma::fragment<wmma::accumulator, 16, 16, 16, float> acc[2][2];
#pragma unroll
    for (int i = 0; i < 2; i++)
#pragma unroll
        for (int j = 0; j < 2; j++) wmma::fill_fragment(acc[i][j], 0.f);

    const int KT = K / BK;
    load_tile(0, 0); cp_commit();

    for (int kt = 0; kt < KT; kt++) {
        cp_wait<0>();
        __syncthreads();             // all data of stage kt&1 visible; prev readers done
        if (kt + 1 < KT) load_tile((kt + 1) & 1, kt + 1);
        cp_commit();

        const int s = kt & 1;
#pragma unroll
        for (int kk = 0; kk < 4; kk++) {
            wmma::fragment<wmma::matrix_a, 16, 16, 16, __half, wmma::row_major> af[2];
            wmma::fragment<wmma::matrix_b, 16, 16, 16, __half, wmma::row_major> bf[2];
#pragma unroll
            for (int i = 0; i < 2; i++)
                wmma::load_matrix_sync(af[i], &sm.in.A[s][wr * 32 + i * 16][kk * 16], BK + 8);
#pragma unroll
            for (int j = 0; j < 2; j++)
                wmma::load_matrix_sync(bf[j], &sm.in.B[s][kk * 16][wc * 32 + j * 16], BN + 8);
#pragma unroll
            for (int i = 0; i < 2; i++)
#pragma unroll
                for (int j = 0; j < 2; j++)
                    wmma::mma_sync(acc[i][j], af[i], bf[j], acc[i][j]);
        }
    }
    __syncthreads();                 // before union re-use as Cs

    // spill accumulators to smem
#pragma unroll
    for (int i = 0; i < 2; i++)
#pragma unroll
        for (int j = 0; j < 2; j++)
            wmma::store_matrix_sync(&sm.Cs[wr * 32 + i * 16][wc * 32 + j * 16],
                                    acc[i][j], BN + 4, wmma::mem_row_major);
    __syncthreads();

    if (!FUSED) {
        // bias + relu + fp16 store, 8 cols/thread (STG.128), 4 iterations
#pragma unroll
        for (int e = tid; e < BM * (BN / 8); e += T) {
            const int r = e >> 3, c = (e & 7) << 3;
            __half h8[8];
#pragma unroll
            for (int q = 0; q < 8; q++) {
                float v = fmaxf(sm.Cs[r][c + q] + bias[colBase + c + q], 0.f);
                h8[q] = __float2half(v);
            }
            *reinterpret_cast<int4*>(&C[(size_t)(rowBase + r) * N + colBase + c]) =
                *reinterpret_cast<int4*>(h8);
        }
    } else {
        // thread -> (row, 32-col segment): 64 rows x 2 segs = 128 threads
        const int r = tid >> 1, sc = (tid & 1) << 5;
        float v = 0.f;
#pragma unroll
        for (int i = 0; i < 32; i++) {
            const float h = fmaxf(sm.Cs[r][sc + i] + bs[sc + i], 0.f);
            v = fmaf(h, w3s[sc + i], v);
        }
        sp[r][tid & 1] = v;
        __syncthreads();
        if (tid < BM)
            g_part[(size_t)blockIdx.x * M + rowBase + tid] = sp[tid][0] + sp[tid][1];
    }
}

// ---------------------------------------------------------------------------
// Deterministic final reduce: out[i] = sum of 4 partials + b3.
// ---------------------------------------------------------------------------
__global__ void __launch_bounds__(256) reduce_kernel(const float* __restrict__ b3,
                                                     float* __restrict__ out)
{
    const int i = blockIdx.x * 256 + threadIdx.x;
    out[i] = ((g_part[i] + g_part[Bsz + i]) + (g_part[2 * Bsz + i] + g_part[3 * Bsz + i]))
             + b3[0];
}

// ---------------------------------------------------------------------------
extern "C" void kernel_launch(void* const* d_in, const int* in_sizes, int n_in,
                              void* d_out, int out_size)
{
    const int*   x    = (const int*)  d_in[0];
    const float* Wphi = (const float*)d_in[1];
    const float* bphi = (const float*)d_in[2];
    const float* W1   = (const float*)d_in[3];
    const float* b1   = (const float*)d_in[4];
    const float* W2   = (const float*)d_in[5];
    const float* b2   = (const float*)d_in[6];
    const float* W3   = (const float*)d_in[7];
    const float* b3   = (const float*)d_in[8];
    float* out = (float*)d_out;

    __half *hist_p, *h1_p, *Wc_p, *W2_p;
    float *b1eff_p;
    cudaGetSymbolAddress((void**)&hist_p,  g_hist);
    cudaGetSymbolAddress((void**)&h1_p,    g_h1);
    cudaGetSymbolAddress((void**)&Wc_p,    g_Wc);
    cudaGetSymbolAddress((void**)&W2_p,    g_W2);
    cudaGetSymbolAddress((void**)&b1eff_p, g_b1eff);

    // Lazily created side stream + fork/join events (resource setup only; the
    // per-call work graph is identical every call). First call is the
    // uncaptured correctness run, so creation happens outside graph capture.
    static cudaStream_t s1 = nullptr;
    static cudaEvent_t evStart = nullptr, evA = nullptr, evB = nullptr, evE = nullptr;
    if (s1 == nullptr) {
        cudaStreamCreateWithFlags(&s1, cudaStreamNonBlocking);
        cudaEventCreateWithFlags(&evStart, cudaEventDisableTiming);
        cudaEventCreateWithFlags(&evA,     cudaEventDisableTiming);
        cudaEventCreateWithFlags(&evB,     cudaEventDisableTiming);
        cudaEventCreateWithFlags(&evE,     cudaEventDisableTiming);
    }

    // Fork: s1 joins the capture via evStart.
    cudaEventRecord(evStart, 0);
    cudaStreamWaitEvent(s1, evStart, 0);

    // s1: weight prep (Wc HMMA + W2 convert + b1eff) — overlaps histA
    prepw_kernel<<<97, 256, 0, s1>>>(Wphi, W1, W2, bphi, b1);

    // s0 (legacy): histogram halves, serialized -> early release of rows A
    hist_kernel<<<512, 128>>>(x, 0);
    cudaEventRecord(evA, 0);
    hist_kernel<<<512, 128>>>(x, 2048);
    cudaEventRecord(evB, 0);

    // s1: GEMM chain, gated per half; overlaps histB on complementary pipes
    cudaStreamWaitEvent(s1, evA, 0);
    {
        dim3 g1(H1d / 64, 2048 / 64);
        gemm_tc<false><<<g1, 128, 0, s1>>>(hist_p, Wc_p, b1eff_p, nullptr,
                                           h1_p, 0, Bsz, H1d, Csz);
        dim3 g2(H2d / 64, 2048 / 64);
        gemm_tc<true><<<g2, 128, 0, s1>>>(h1_p, W2_p, b2, W3,
                                          nullptr, 0, Bsz, H2d, H1d);
    }
    cudaStreamWaitEvent(s1, evB, 0);
    {
        dim3 g1(H1d / 64, 2048 / 64);
        gemm_tc<false><<<g1, 128, 0, s1>>>(hist_p, Wc_p, b1eff_p, nullptr,
                                           h1_p, 2048, Bsz, H1d, Csz);
        dim3 g2(H2d / 64, 2048 / 64);
        gemm_tc<true><<<g2, 128, 0, s1>>>(h1_p, W2_p, b2, W3,
                                          nullptr, 2048, Bsz, H2d, H1d);
    }
    reduce_kernel<<<Bsz / 256, 256, 0, s1>>>(b3, out);

    // Join back to the capture-origin stream.
    cudaEventRecord(evE, s1);
    cudaStreamWaitEvent(0, evE, 0);
}

// round 15
// speedup vs baseline: 1.2557x; 1.2557x over previous
#include <cuda_runtime.h>
#include <cuda_fp16.h>
#include <mma.h>

using namespace nvcuda;

#define Bsz  4096
#define Nseq 512
#define Csz  512
#define PHId 128
#define H1d  512
#define H2d  256

// Scratch (__device__ globals; no allocations allowed)
__device__ __half g_hist [Bsz * Csz];    // 4 MB   per-row label histogram (fp16, exact)
__device__ __half g_h1   [Bsz * H1d];    // 4 MB
__device__ float  g_part [4 * Bsz];      // partial dots (deterministic reduce)
__device__ __half g_Wc   [Csz * H1d];    // 512 KB  Wc = Wphi @ W1 (fp16)
__device__ __half g_W2   [H1d * H2d];
__device__ float  g_b1eff[H1d];          // b1 + 512 * (b_phi @ W1), exact fp32

// ---------------------------------------------------------------------------
// cp.async helpers (LDGSTS, 16B)
// ---------------------------------------------------------------------------
__device__ __forceinline__ void cp_async16(void* smem, const void* gmem) {
    unsigned s = (unsigned)__cvta_generic_to_shared(smem);
    asm volatile("cp.async.cg.shared.global [%0], [%1], 16;\n" :: "r"(s), "l"(gmem));
}
__device__ __forceinline__ void cp_commit() {
    asm volatile("cp.async.commit_group;\n");
}
template <int NN>
__device__ __forceinline__ void cp_wait() {
    asm volatile("cp.async.wait_group %0;\n" :: "n"(NN));
}

// ---------------------------------------------------------------------------
// Prep kernel, block ranges:
//   [0,512)   : per-row histograms (8 rows/block, smem atomics) -> g_hist fp16
//   [512,576) : Wc = Wphi @ W1 via wmma HMMA (fp16 in, fp32 acc), 64x64/block
//   [576,608) : W2 fp32 -> fp16 convert
//   608       : b1_eff = b1 + 512*(b_phi @ W1) in fp32
// ---------------------------------------------------------------------------
__global__ void __launch_bounds__(256) prep_kernel(const int* __restrict__ x,
                                                   const float* __restrict__ Wphi,
                                                   const float* __restrict__ W1,
                                                   const float* __restrict__ W2,
                                                   const float* __restrict__ bphi,
                                                   const float* __restrict__ b1)
{
    __shared__ __align__(16) char praw[35840];   // 35 KB, aliased per branch
    const int tid = threadIdx.x;

    if (blockIdx.x < 512) {
        int* hs = reinterpret_cast<int*>(praw);  // [8][512]
#pragma unroll
        for (int i = 0; i < 4; i++)
            reinterpret_cast<int4*>(hs)[tid + i * 256] = make_int4(0, 0, 0, 0);
        __syncthreads();

        const int warp = tid >> 5, lane = tid & 31;
        const int row = blockIdx.x * 8 + warp;
        const int4* xr = reinterpret_cast<const int4*>(x + (size_t)row * Nseq);
        int* hw = hs + warp * Csz;
#pragma unroll
        for (int i = 0; i < 4; i++) {            // 128 int4 per row
            const int4 v = xr[lane + i * 32];
            atomicAdd(&hw[v.x], 1);
            atomicAdd(&hw[v.y], 1);
            atomicAdd(&hw[v.z], 1);
            atomicAdd(&hw[v.w], 1);
        }
        __syncthreads();

        // vectorized fp16 conversion: 1024 int4 -> 1024 x 8B stores
        __half* dst = g_hist + (size_t)blockIdx.x * 8 * Csz;
#pragma unroll
        for (int i = 0; i < 4; i++) {
            const int e4 = tid + i * 256;
            const int4 c = reinterpret_cast<const int4*>(hs)[e4];
            __half h4[4] = {__float2half((float)c.x), __float2half((float)c.y),
                            __float2half((float)c.z), __float2half((float)c.w)};
            *reinterpret_cast<uint2*>(&dst[e4 * 4]) = *reinterpret_cast<uint2*>(h4);
        }
    } else if (blockIdx.x < 576) {
        // Wc tile 64x64, K=128, tensor cores. smem: A[64][136]h, B[128][72]h
        const int cb = blockIdx.x - 512;               // 0..63 -> 8x8 tiles
        const int tr = (cb >> 3) * 64, tcc = (cb & 7) * 64;
        __half* sA = reinterpret_cast<__half*>(praw);           // ld 136
        __half* sB = reinterpret_cast<__half*>(praw + 17408);   // ld 72
        float*  sC = reinterpret_cast<float*>(praw);            // ld 68 (aliases sA)

#pragma unroll
        for (int i = 0; i < 8; i++) {
            const int idx = i * 256 + tid;
            const int r = idx >> 5, c4 = (idx & 31) << 2;
            const float4 v = *reinterpret_cast<const float4*>(
                &Wphi[(size_t)(tr + r) * PHId + c4]);
            __half h4[4] = {__float2half(v.x), __float2half(v.y),
                            __float2half(v.z), __float2half(v.w)};
            *reinterpret_cast<uint2*>(&sA[r * 136 + c4]) = *reinterpret_cast<uint2*>(h4);
        }
#pragma unroll
        for (int i = 0; i < 8; i++) {
            const int idx = i * 256 + tid;
            const int r = idx >> 4, c4 = (idx & 15) << 2;
            const float4 v = *reinterpret_cast<const float4*>(
                &W1[(size_t)r * H1d + tcc + c4]);
            __half h4[4] = {__float2half(v.x), __float2half(v.y),
                            __float2half(v.z), __float2half(v.w)};
            *reinterpret_cast<uint2*>(&sB[r * 72 + c4]) = *reinterpret_cast<uint2*>(h4);
        }
        __syncthreads();

        // 8 warps: 2 row-groups x 4 col-groups; warp tile 32x16
        const int wrp = tid >> 5, wr2 = wrp & 1, wc2 = wrp >> 1;
        wmma::fragment<wmma::accumulator, 16, 16, 16, float> ac[2];
        wmma::fill_fragment(ac[0], 0.f);
        wmma::fill_fragment(ac[1], 0.f);
#pragma unroll
        for (int k = 0; k < 8; k++) {
            wmma::fragment<wmma::matrix_a, 16, 16, 16, __half, wmma::row_major> af[2];
            wmma::fragment<wmma::matrix_b, 16, 16, 16, __half, wmma::row_major> bf;
            wmma::load_matrix_sync(af[0], &sA[(wr2 * 32) * 136 + k * 16], 136);
            wmma::load_matrix_sync(af[1], &sA[(wr2 * 32 + 16) * 136 + k * 16], 136);
            wmma::load_matrix_sync(bf, &sB[(k * 16) * 72 + wc2 * 16], 72);
            wmma::mma_sync(ac[0], af[0], bf, ac[0]);
            wmma::mma_sync(ac[1], af[1], bf, ac[1]);
        }
        __syncthreads();       // done reading sA before aliasing as sC
        wmma::store_matrix_sync(&sC[(wr2 * 32) * 68 + wc2 * 16], ac[0], 68,
                                wmma::mem_row_major);
        wmma::store_matrix_sync(&sC[(wr2 * 32 + 16) * 68 + wc2 * 16], ac[1], 68,
                                wmma::mem_row_major);
        __syncthreads();

#pragma unroll
        for (int e = tid; e < 64 * 8; e += 256) {
            const int r = e >> 3, c = (e & 7) << 3;
            __half h8[8];
#pragma unroll
            for (int q = 0; q < 8; q++) h8[q] = __float2half(sC[r * 68 + c + q]);
            *reinterpret_cast<int4*>(&g_Wc[(size_t)(tr + r) * H1d + tcc + c]) =
                *reinterpret_cast<int4*>(h8);
        }
    } else if (blockIdx.x < 608) {
        // W2 convert: 8192 threads, 32768 float4 -> 4 per thread
        const int t = (blockIdx.x - 576) * 256 + tid;
#pragma unroll
        for (int i = 0; i < 4; i++) {
            const int e4 = t + i * 8192;
            const float4 v = reinterpret_cast<const float4*>(W2)[e4];
            __half h4[4] = {__float2half(v.x), __float2half(v.y),
                            __float2half(v.z), __float2half(v.w)};
            *reinterpret_cast<uint2*>(&g_W2[e4 * 4]) = *reinterpret_cast<uint2*>(h4);
        }
    } else {
#pragma unroll
        for (int o = tid; o < H1d; o += 256) {
            float s = 0.f;
            for (int k = 0; k < PHId; k++) s = fmaf(bphi[k], W1[k * H1d + o], s);
            g_b1eff[o] = b1[o] + (float)Nseq * s;
        }
    }
}

// ---------------------------------------------------------------------------
// Pipelined fp16 tensor-core GEMM, fp32 accumulate, fused bias+ReLU epilogue.
// BM=64, BN=64, BK=64; 128 threads = 4 warps (2x2), warp tile 32x32.
// 2-buffer pipeline with TWO loads in flight: per iter
//   sync (frees buf (kt+1)&1) -> issue load(kt+1) -> commit -> wait<1>
//   -> sync (tile kt visible) -> compute kt.
// FUSED: epilogue computes relu(acc+bias) dot W3-slice -> g_part.
// ---------------------------------------------------------------------------
template <bool FUSED>
__global__ void __launch_bounds__(128) gemm_tc(const __half* __restrict__ A,
                                               const __half* __restrict__ B,
                                               const float* __restrict__ bias,
                                               const float* __restrict__ W3,
                                               __half* __restrict__ C,
                                               int M, int N, int K)
{
    constexpr int BM = 64, BN = 64, BK = 64, T = 128;
    __shared__ __align__(16) union USM {
        struct { __half A[2][BM][BK + 8]; __half B[2][BK][BN + 8]; } in;   // 36 KB
        float Cs[BM][BN + 4];
    } sm;
    __shared__ float w3s[BN];
    __shared__ float bs[BN];
    __shared__ float sp[BM][2];

    const int tid  = threadIdx.x;
    const int warp = tid >> 5;
    const int wr   = warp & 1;      // row group: 32 rows
    const int wc   = warp >> 1;     // col group: 32 cols
    const int rowBase = blockIdx.y * BM;
    const int colBase = blockIdx.x * BN;

    if (FUSED && tid < BN) {
        w3s[tid] = W3[colBase + tid];
        bs[tid]  = bias[colBase + tid];
    }

    // loader map: 64 rows x 8 chunks(16B) = 512 chunks, 4 per thread
    const int lr = tid >> 3, lc = (tid & 7) << 3;

    auto load_tile = [&](int s, int kt) {
        const __half* Ak = A + (size_t)rowBase * K + kt * BK;
#pragma unroll
        for (int r = 0; r < 4; r++)
            cp_async16(&sm.in.A[s][lr + 16 * r][lc], Ak + (size_t)(lr + 16 * r) * K + lc);
        const __half* Bk = B + (size_t)(kt * BK) * N + colBase;
#pragma unroll
        for (int r = 0; r < 4; r++)
            cp_async16(&sm.in.B[s][lr + 16 * r][lc], Bk + (size_t)(lr + 16 * r) * N + lc);
    };

    wmma::fragment<wmma::accumulator, 16, 16, 16, float> acc[2][2];
#pragma unroll
    for (int i = 0; i < 2; i++)
#pragma unroll
        for (int j = 0; j < 2; j++) wmma::fill_fragment(acc[i][j], 0.f);

    const int KT = K / BK;
    load_tile(0, 0); cp_commit();

    for (int kt = 0; kt < KT; kt++) {
        __syncthreads();             // all warps done computing tile kt-1
                                     // -> buffer (kt+1)&1 is safe to overwrite
        if (kt + 1 < KT) load_tile((kt + 1) & 1, kt + 1);
        cp_commit();                 // (possibly empty) keeps group count uniform
        cp_wait<1>();                // tile kt landed; tile kt+1 stays in flight
        __syncthreads();             // cross-warp visibility of tile kt

        const int s = kt & 1;
#pragma unroll
        for (int kk = 0; kk < 4; kk++) {
            wmma::fragment<wmma::matrix_a, 16, 16, 16, __half, wmma::row_major> af[2];
            wmma::fragment<wmma::matrix_b, 16, 16, 16, __half, wmma::row_major> bf[2];
#pragma unroll
            for (int i = 0; i < 2; i++)
                wmma::load_matrix_sync(af[i], &sm.in.A[s][wr * 32 + i * 16][kk * 16], BK + 8);
#pragma unroll
            for (int j = 0; j < 2; j++)
                wmma::load_matrix_sync(bf[j], &sm.in.B[s][kk * 16][wc * 32 + j * 16], BN + 8);
#pragma unroll
            for (int i = 0; i < 2; i++)
#pragma unroll
                for (int j = 0; j < 2; j++)
                    wmma::mma_sync(acc[i][j], af[i], bf[j], acc[i][j]);
        }
    }
    cp_wait<0>();                    // drain any stragglers before buffer reuse
    __syncthreads();                 // before union re-use as Cs

    // spill accumulators to smem
#pragma unroll
    for (int i = 0; i < 2; i++)
#pragma unroll
        for (int j = 0; j < 2; j++)
            wmma::store_matrix_sync(&sm.Cs[wr * 32 + i * 16][wc * 32 + j * 16],
                                    acc[i][j], BN + 4, wmma::mem_row_major);
    __syncthreads();

    if (!FUSED) {
        // bias + relu + fp16 store, 8 cols/thread (STG.128), 4 iterations
#pragma unroll
        for (int e = tid; e < BM * (BN / 8); e += T) {
            const int r = e >> 3, c = (e & 7) << 3;
            __half h8[8];
#pragma unroll
            for (int q = 0; q < 8; q++) {
                float v = fmaxf(sm.Cs[r][c + q] + bias[colBase + c + q], 0.f);
                h8[q] = __float2half(v);
            }
            *reinterpret_cast<int4*>(&C[(size_t)(rowBase + r) * N + colBase + c]) =
                *reinterpret_cast<int4*>(h8);
        }
    } else {
        // thread -> (row, 32-col segment): 64 rows x 2 segs = 128 threads
        const int r = tid >> 1, sc = (tid & 1) << 5;
        float v = 0.f;
#pragma unroll
        for (int i = 0; i < 32; i++) {
            const float h = fmaxf(sm.Cs[r][sc + i] + bs[sc + i], 0.f);
            v = fmaf(h, w3s[sc + i], v);
        }
        sp[r][tid & 1] = v;
        __syncthreads();
        if (tid < BM)
            g_part[(size_t)blockIdx.x * M + rowBase + tid] = sp[tid][0] + sp[tid][1];
    }
}

// ---------------------------------------------------------------------------
// Deterministic final reduce: out[i] = sum of 4 partials + b3.
// ---------------------------------------------------------------------------
__global__ void __launch_bounds__(256) reduce_kernel(const float* __restrict__ b3,
                                                     float* __restrict__ out)
{
    const int i = blockIdx.x * 256 + threadIdx.x;
    out[i] = ((g_part[i] + g_part[Bsz + i]) + (g_part[2 * Bsz + i] + g_part[3 * Bsz + i]))
             + b3[0];
}

// ---------------------------------------------------------------------------
extern "C" void kernel_launch(void* const* d_in, const int* in_sizes, int n_in,
                              void* d_out, int out_size)
{
    const int*   x    = (const int*)  d_in[0];
    const float* Wphi = (const float*)d_in[1];
    const float* bphi = (const float*)d_in[2];
    const float* W1   = (const float*)d_in[3];
    const float* b1   = (const float*)d_in[4];
    const float* W2   = (const float*)d_in[5];
    const float* b2   = (const float*)d_in[6];
    const float* W3   = (const float*)d_in[7];
    const float* b3   = (const float*)d_in[8];
    float* out = (float*)d_out;

    __half *hist_p, *h1_p, *Wc_p, *W2_p;
    float *b1eff_p;
    cudaGetSymbolAddress((void**)&hist_p,  g_hist);
    cudaGetSymbolAddress((void**)&h1_p,    g_h1);
    cudaGetSymbolAddress((void**)&Wc_p,    g_Wc);
    cudaGetSymbolAddress((void**)&W2_p,    g_W2);
    cudaGetSymbolAddress((void**)&b1eff_p, g_b1eff);

    // 0: histograms + Wc = Wphi@W1 (HMMA) + W2 convert + b1_eff
    prep_kernel<<<609, 256>>>(x, Wphi, W1, W2, bphi, b1);

    // 1: h1 = relu(hist @ Wc + b1_eff)   (4096x512)@(512x512) -> 512 blocks
    {
        dim3 grid(H1d / 64, Bsz / 64);
        gemm_tc<false><<<grid, 128>>>(hist_p, Wc_p, b1eff_p, nullptr,
                                      h1_p, Bsz, H1d, Csz);
    }
    // 2: fused h2 = relu(h1 @ W2 + b2); partials = h2 @ W3 -> 256 blocks
    {
        dim3 grid(H2d / 64, Bsz / 64);
        gemm_tc<true><<<grid, 128>>>(h1_p, W2_p, b2, W3,
                                     nullptr, Bsz, H2d, H1d);
    }
    // 3: deterministic reduce + b3
    reduce_kernel<<<Bsz / 256, 256>>>(b3, out);
}